// round 14
// baseline (speedup 1.0000x reference)
#include <cuda_runtime.h>
#include <cstdint>

#define DIM   512
#define BATCH 32
#define TT    2048
#define NBLK  128
#define RTHR  1024              // 32 warps: warp = (kh = w>>1, bh = w&1)

// ---------------- device scratch (no allocations allowed) ----------------
__device__ __align__(16) float g_xT[(size_t)TT * DIM * BATCH];  // [t][k4][b][4]
__device__ __align__(16) float g_hbuf[4][DIM * BATCH];          // [k4][b][4]
__device__ unsigned g_flag[NBLK * 8];   // one flag per block, 32B apart

typedef unsigned long long ull;

// ---------------- f32x2 helpers ----------------
__device__ __forceinline__ ull f2fma(ull a, ull b, ull c){
    ull d; asm("fma.rn.f32x2 %0, %1, %2, %3;" : "=l"(d) : "l"(a), "l"(b), "l"(c)); return d;
}
__device__ __forceinline__ float2 upk(ull v){
    float2 f; asm("mov.b64 {%0, %1}, %2;" : "=f"(f.x), "=f"(f.y) : "l"(v)); return f;
}
__device__ __forceinline__ float hadd(ull v){ float2 f = upk(v); return f.x + f.y; }

__device__ __forceinline__ float sigf(float x){ return 1.0f / (1.0f + __expf(-x)); }
__device__ __forceinline__ float tanhfast(float x){
    float e = __expf(2.0f * x);              // inf-safe at both ends
    return 1.0f - 2.0f / (e + 1.0f);
}

// ---------------- scoped sync primitives ----------------
__device__ __forceinline__ void st_release(unsigned* p, unsigned v){
    asm volatile("st.release.gpu.global.u32 [%0], %1;" :: "l"(p), "r"(v) : "memory");
}
__device__ __forceinline__ unsigned ld_acquire(unsigned* p){
    unsigned v;
    asm volatile("ld.acquire.gpu.global.u32 %0, [%1];" : "=r"(v) : "l"(p) : "memory");
    return v;
}
__device__ __forceinline__ void cpa16(unsigned dst, const void* src){
    asm volatile("cp.async.cg.shared.global [%0], [%1], 16;" :: "r"(dst), "l"(src));
}

// =====================================================================
// Kernel 1: transpose x[b][t][k] -> xT[t][k4][b][4]; block 0 inits state.
// =====================================================================
__global__ void __launch_bounds__(256) xt_kernel(const float* __restrict__ x)
{
    if (blockIdx.x == 0){
        int tid = threadIdx.x;
        for (int i = tid; i < DIM * BATCH; i += 256) g_hbuf[0][i] = 0.0f;
        for (int i = tid; i < NBLK; i += 256) g_flag[i * 8] = 0u;
    }
    size_t gidx = (size_t)blockIdx.x * 256 + threadIdx.x;
    int b  = (int)(gidx & 31);
    int k4 = (int)((gidx >> 5) & 127);
    int t  = (int)(gidx >> 12);
    float4 v = *(const float4*)(x + (size_t)b * ((size_t)TT * DIM)
                                  + (size_t)t * DIM + k4 * 4);
    ((float4*)g_xT)[gidx] = v;
}

// =====================================================================
// Kernel 2: fused persistent LSTM (R11 dataflow, 2x warps).
// 128 blocks x 1024 threads. Warp w: kh = w>>1 (k-slice [kh*32,+32)),
// bh = w&1 (batch half). Lane: bq = l&7, dl = l>>3.
// Thread: 4 gates x 2 batches (b = bh*16+bq+8j) x dim bx*4+dl over
// 32 k, x-phase + h-phase into same acc[4][2].
// Each warp polls 8 producer flags and cp.asyncs its own 2KB slice
// (8 k4 x 16 b) of x and h. Partials shR stride 527 (max col 526).
// Reduce: tid<512 = one (g,d,b) each. Owners tid<128 c/h update.
// Three __syncthreads per step, release after bar3 (R11-proven).
// =====================================================================
__global__ void __launch_bounds__(RTHR) lstm_rec_kernel(
    const float* __restrict__ Wih, const float* __restrict__ Whh,
    const float* __restrict__ bih, const float* __restrict__ bhh,
    float* __restrict__ out)
{
    extern __shared__ float sm[];
    float* shW = sm;              // 16384 fl: f4 idx k4*16+rl ; +2048 f4 = Wih
    float* shH = sm + 16384;      // 16384 fl: [k4][b][4]
    float* shX = sm + 32768;      // 16384 fl: [k4][b][4]
    float* shR = sm + 49152;      // 16 rows x 527
    float* shG = sm + 57584;      // 512 gate values [g*128 + d*32 + b]
    float* shB = sm + 58096;      // 16 biases

    const int tid  = threadIdx.x;
    const int bx   = blockIdx.x;
    const int w    = tid >> 5;
    const int kh   = w >> 1;
    const int bh   = w & 1;
    const int lane = tid & 31;
    const int bq   = lane & 7;
    const int dl   = lane >> 3;

    // Load W_hh and W_ih slices into [k4][rl] layout (once).
    for (int idx = tid; idx < 4096; idx += RTHR){
        int half = idx >> 11;              // 0 = hh, 1 = ih
        int rem  = idx & 2047;
        int rl   = rem >> 7;               // g*4 + dloc
        int k4   = rem & 127;
        int g = rl >> 2, dloc = rl & 3;
        const float* src = (half ? Wih : Whh)
                         + (size_t)(g * DIM + bx * 4 + dloc) * DIM + k4 * 4;
        ((float4*)shW)[half * 2048 + k4 * 16 + rl] = *(const float4*)src;
    }
    if (tid < 16){
        int n = (tid >> 2) * DIM + bx * 4 + (tid & 3);
        shB[tid] = bih[n] + bhh[n];
    }

    // FMA bases (single base + immediate offsets keeps regs low)
    const ulonglong2* WB = (const ulonglong2*)shW + kh * 128 + dl;  // + i*16 + g*4
    const ulonglong2* hp = (const ulonglong2*)shH + kh * 256 + bh * 16 + bq;
    const ulonglong2* xp = (const ulonglong2*)shX + kh * 256 + bh * 16 + bq;

    // staging: warp's 128-f4 slice (8 k4 x 16 b); 4 cpa per lane
    const int sidx = kh * 256 + bh * 16 + (lane >> 4) * 32 + (lane & 15);
    const unsigned stH =
        (unsigned)__cvta_generic_to_shared(shH) + (unsigned)sidx * 16u;
    const unsigned stX =
        (unsigned)__cvta_generic_to_shared(shX) + (unsigned)sidx * 16u;

    // poll: producers of k-slice kh are blocks kh*8 .. kh*8+7
    unsigned* pf = &g_flag[(kh * 8 + (lane & 7)) * 8];

    // reduce role (tid < 512): one (rg, rd, rb)
    const int rg = tid >> 7;
    const int rd = (tid >> 5) & 3;
    const int rb = tid & 31;
    const float* rp = shR + (rg * 4 + (rb >> 3)) * 527 + rd * 8 + (rb & 7);

    // owner role (tid < 128): pb = tid&31, pd = tid>>5
    const int pb = tid & 31;
    const int pd = tid >> 5;
    float* outp = out + (size_t)pb * ((size_t)TT * DIM) + (bx * 4 + pd);
    const int hwidx = bx * 128 + pb * 4 + pd;

    float cc = 0.0f;

    // prologue: stage x for t = 0
    {
        const float4* xs = (const float4*)g_xT + sidx;
        #pragma unroll
        for (int q = 0; q < 4; q++) cpa16(stX + q * 1024u, xs + q * 64);
        asm volatile("cp.async.commit_group;");
    }
    __syncthreads();                       // W + biases ready

    for (int t = 0; t < TT; t++){
        asm volatile("cp.async.wait_group 0;");
        __syncwarp();

        ull acc[4][2];
        #pragma unroll
        for (int g = 0; g < 4; g++){ acc[g][0] = 0ULL; acc[g][1] = 0ULL; }

        // ---- x-FMA: 4 gates x 2 batches over 32 k ----
        #pragma unroll
        for (int i = 0; i < 8; i++){
            ulonglong2 x0 = xp[i * 32];
            ulonglong2 x1 = xp[i * 32 + 8];
            ulonglong2 v0 = WB[2048 + i * 16];
            ulonglong2 v1 = WB[2048 + i * 16 + 4];
            ulonglong2 v2 = WB[2048 + i * 16 + 8];
            ulonglong2 v3 = WB[2048 + i * 16 + 12];
            acc[0][0]=f2fma(x0.x,v0.x,acc[0][0]); acc[0][0]=f2fma(x0.y,v0.y,acc[0][0]);
            acc[0][1]=f2fma(x1.x,v0.x,acc[0][1]); acc[0][1]=f2fma(x1.y,v0.y,acc[0][1]);
            acc[1][0]=f2fma(x0.x,v1.x,acc[1][0]); acc[1][0]=f2fma(x0.y,v1.y,acc[1][0]);
            acc[1][1]=f2fma(x1.x,v1.x,acc[1][1]); acc[1][1]=f2fma(x1.y,v1.y,acc[1][1]);
            acc[2][0]=f2fma(x0.x,v2.x,acc[2][0]); acc[2][0]=f2fma(x0.y,v2.y,acc[2][0]);
            acc[2][1]=f2fma(x1.x,v2.x,acc[2][1]); acc[2][1]=f2fma(x1.y,v2.y,acc[2][1]);
            acc[3][0]=f2fma(x0.x,v3.x,acc[3][0]); acc[3][0]=f2fma(x0.y,v3.y,acc[3][0]);
            acc[3][1]=f2fma(x1.x,v3.x,acc[3][1]); acc[3][1]=f2fma(x1.y,v3.y,acc[3][1]);
        }

        // ---- prefetch x for t+1 ----
        {
            int tn = (t + 1 < TT) ? (t + 1) : t;
            const float4* xs = (const float4*)g_xT + (size_t)tn * 4096 + sidx;
            #pragma unroll
            for (int q = 0; q < 4; q++) cpa16(stX + q * 1024u, xs + q * 64);
            asm volatile("cp.async.commit_group;");
        }

        // ---- poll my 8 producers, stage h ----
        if (lane < 8){
            while (ld_acquire(pf) < (unsigned)t) { }
        }
        __syncwarp();
        {
            const float4* hs = (const float4*)g_hbuf[t & 3] + sidx;
            #pragma unroll
            for (int q = 0; q < 4; q++) cpa16(stH + q * 1024u, hs + q * 64);
            asm volatile("cp.async.commit_group;");
            asm volatile("cp.async.wait_group 0;");
        }
        __syncwarp();

        // ---- h-FMA into same accumulators ----
        #pragma unroll
        for (int i = 0; i < 8; i++){
            ulonglong2 h0 = hp[i * 32];
            ulonglong2 h1 = hp[i * 32 + 8];
            ulonglong2 v0 = WB[i * 16];
            ulonglong2 v1 = WB[i * 16 + 4];
            ulonglong2 v2 = WB[i * 16 + 8];
            ulonglong2 v3 = WB[i * 16 + 12];
            acc[0][0]=f2fma(h0.x,v0.x,acc[0][0]); acc[0][0]=f2fma(h0.y,v0.y,acc[0][0]);
            acc[0][1]=f2fma(h1.x,v0.x,acc[0][1]); acc[0][1]=f2fma(h1.y,v0.y,acc[0][1]);
            acc[1][0]=f2fma(h0.x,v1.x,acc[1][0]); acc[1][0]=f2fma(h0.y,v1.y,acc[1][0]);
            acc[1][1]=f2fma(h1.x,v1.x,acc[1][1]); acc[1][1]=f2fma(h1.y,v1.y,acc[1][1]);
            acc[2][0]=f2fma(h0.x,v2.x,acc[2][0]); acc[2][0]=f2fma(h0.y,v2.y,acc[2][0]);
            acc[2][1]=f2fma(h1.x,v2.x,acc[2][1]); acc[2][1]=f2fma(h1.y,v2.y,acc[2][1]);
            acc[3][0]=f2fma(h0.x,v3.x,acc[3][0]); acc[3][0]=f2fma(h0.y,v3.y,acc[3][0]);
            acc[3][1]=f2fma(h1.x,v3.x,acc[3][1]); acc[3][1]=f2fma(h1.y,v3.y,acc[3][1]);
        }

        // ---- partials: row = g*4 + (bh*2 + j), col = kh*33 + lane ----
        #pragma unroll
        for (int g = 0; g < 4; g++){
            shR[(g*4 + bh*2 + 0) * 527 + kh * 33 + lane] = hadd(acc[g][0]);
            shR[(g*4 + bh*2 + 1) * 527 + kh * 33 + lane] = hadd(acc[g][1]);
        }
        __syncthreads();                   // bar1: all partials in

        // ---- reduce (tid<512): one (g,d,b) each, 16 partials + bias ----
        if (tid < 512){
            float s = shB[rg * 4 + rd];
            #pragma unroll
            for (int k = 0; k < 16; k++) s += rp[k * 33];
            shG[rg * 128 + rd * 32 + rb] = (rg == 2) ? tanhfast(s) : sigf(s);
        }
        __syncthreads();                   // bar2: gates ready

        // ---- owners: c/h update, store h ----
        float hv = 0.0f;
        if (tid < 128){
            float iv = shG[  0 + pd * 32 + pb];
            float fv = shG[128 + pd * 32 + pb];
            float gv = shG[256 + pd * 32 + pb];
            float ov = shG[384 + pd * 32 + pb];
            cc = fv * cc + iv * gv;
            hv = ov * tanhfast(cc);
            g_hbuf[(t + 1) & 3][hwidx] = hv;
        }
        __syncthreads();                   // bar3: h stores done block-wide

        if (t + 1 < TT){
            if (tid == 0) st_release(&g_flag[bx * 8], (unsigned)(t + 1));
        }
        // out store overlaps the next step's x-FMA/polls
        if (tid < 128) outp[(size_t)t * DIM] = hv;
    }
}

// =====================================================================
extern "C" void kernel_launch(void* const* d_in, const int* in_sizes, int n_in,
                              void* d_out, int out_size)
{
    (void)in_sizes; (void)n_in; (void)out_size;
    const float* x    = (const float*)d_in[0];
    const float* Wih  = (const float*)d_in[1];
    const float* Whh  = (const float*)d_in[2];
    const float* bih  = (const float*)d_in[3];
    const float* bhh  = (const float*)d_in[4];
    float* out = (float*)d_out;

    // 16384 + 16384 + 16384 + 8432 + 512 + 16 = 58112 floats = 232448 bytes
    cudaFuncSetAttribute(lstm_rec_kernel,
                         cudaFuncAttributeMaxDynamicSharedMemorySize, 232448);

    xt_kernel<<<(TT * DIM * BATCH / 4) / 256, 256>>>(x);
    lstm_rec_kernel<<<NBLK, RTHR, 232448>>>(Wih, Whh, bih, bhh, out);
}

// round 15
// speedup vs baseline: 1.1613x; 1.1613x over previous
#include <cuda_runtime.h>
#include <cstdint>

#define DIM   512
#define BATCH 32
#define TT    2048
#define NBLK  128
#define RTHR  512

// ---------------- device scratch (no allocations allowed) ----------------
__device__ __align__(16) float g_xT[(size_t)TT * DIM * BATCH];  // [t][k4][b][4]
__device__ __align__(16) float g_hbuf[4][DIM * BATCH];          // [k4][b][4]
__device__ unsigned g_flag[NBLK * 8];   // one flag per block, 32B apart

typedef unsigned long long ull;

// ---------------- f32x2 helpers ----------------
__device__ __forceinline__ ull f2fma(ull a, ull b, ull c){
    ull d; asm("fma.rn.f32x2 %0, %1, %2, %3;" : "=l"(d) : "l"(a), "l"(b), "l"(c)); return d;
}
__device__ __forceinline__ float2 upk(ull v){
    float2 f; asm("mov.b64 {%0, %1}, %2;" : "=f"(f.x), "=f"(f.y) : "l"(v)); return f;
}
__device__ __forceinline__ float hadd(ull v){ float2 f = upk(v); return f.x + f.y; }

__device__ __forceinline__ float sigf(float x){ return 1.0f / (1.0f + __expf(-x)); }
__device__ __forceinline__ float tanhfast(float x){
    float e = __expf(2.0f * x);              // inf-safe at both ends
    return 1.0f - 2.0f / (e + 1.0f);
}

// ---------------- scoped sync primitives ----------------
__device__ __forceinline__ void st_release(unsigned* p, unsigned v){
    asm volatile("st.release.gpu.global.u32 [%0], %1;" :: "l"(p), "r"(v) : "memory");
}
__device__ __forceinline__ unsigned ld_acquire(unsigned* p){
    unsigned v;
    asm volatile("ld.acquire.gpu.global.u32 %0, [%1];" : "=r"(v) : "l"(p) : "memory");
    return v;
}
__device__ __forceinline__ void cpa16(unsigned dst, const void* src){
    asm volatile("cp.async.cg.shared.global [%0], [%1], 16;" :: "r"(dst), "l"(src));
}

// =====================================================================
// Kernel 1: transpose x[b][t][k] -> xT[t][k4][b][4]; block 0 inits state.
// =====================================================================
__global__ void __launch_bounds__(256) xt_kernel(const float* __restrict__ x)
{
    if (blockIdx.x == 0){
        int tid = threadIdx.x;
        for (int i = tid; i < DIM * BATCH; i += 256) g_hbuf[0][i] = 0.0f;
        for (int i = tid; i < NBLK; i += 256) g_flag[i * 8] = 0u;
    }
    size_t gidx = (size_t)blockIdx.x * 256 + threadIdx.x;
    int b  = (int)(gidx & 31);
    int k4 = (int)((gidx >> 5) & 127);
    int t  = (int)(gidx >> 12);
    float4 v = *(const float4*)(x + (size_t)b * ((size_t)TT * DIM)
                                  + (size_t)t * DIM + k4 * 4);
    ((float4*)g_xT)[gidx] = v;
}

// =====================================================================
// Kernel 2: fused persistent LSTM — R11 base + split-h pipelining +
// early release via 128-thread named barrier.
// 128 blocks x 512 threads; warp kh owns k-slice [kh*32,+32) (k4
// [kh*8,+8)); lane = (bq = l&7, dl = l>>3); 4 gates x 4 batches x
// dim bx*4+dl. h staged in two 2KB halves: poll half producers ->
// cp.async -> overlap FMA(h1) with stage(h2). Reduce tid<512; owners
// tid<128 -> bar.sync 3,128 -> release -> out store (warps 4-15 race
// ahead; ring safety by 1-hop poll coverage of all 128 flags).
// =====================================================================
__global__ void __launch_bounds__(RTHR) lstm_rec_kernel(
    const float* __restrict__ Wih, const float* __restrict__ Whh,
    const float* __restrict__ bih, const float* __restrict__ bhh,
    float* __restrict__ out)
{
    extern __shared__ float sm[];
    float* shW = sm;              // 16384 fl: f4 idx k4*16+rl ; +2048 f4 = Wih
    float* shH = sm + 16384;      // 16384 fl: [k4][b][4]
    float* shX = sm + 32768;      // 16384 fl: [k4][b][4]
    float* shR = sm + 49152;      // 16 rows x 527
    float* shG = sm + 57584;      // 512 gate values [g*128 + d*32 + b]
    float* shB = sm + 58096;      // 16 biases

    const int tid  = threadIdx.x;
    const int bx   = blockIdx.x;
    const int kh   = tid >> 5;
    const int lane = tid & 31;
    const int bq   = lane & 7;
    const int dl   = lane >> 3;

    // Load W_hh and W_ih slices into [k4][rl] layout (once).
    for (int idx = tid; idx < 4096; idx += RTHR){
        int half = idx >> 11;              // 0 = hh, 1 = ih
        int rem  = idx & 2047;
        int rl   = rem >> 7;               // g*4 + dloc
        int k4   = rem & 127;
        int g = rl >> 2, dloc = rl & 3;
        const float* src = (half ? Wih : Whh)
                         + (size_t)(g * DIM + bx * 4 + dloc) * DIM + k4 * 4;
        ((float4*)shW)[half * 2048 + k4 * 16 + rl] = *(const float4*)src;
    }
    if (tid < 16){
        int n = (tid >> 2) * DIM + bx * 4 + (tid & 3);
        shB[tid] = bih[n] + bhh[n];
    }

    // FMA pointers: f4 idx = (kh*8+i)*16 + g*4 + dl
    const ulonglong2* WH = (const ulonglong2*)shW;
    const ulonglong2* wh0 = WH + kh*128 + 0*4 + dl;
    const ulonglong2* wh1 = WH + kh*128 + 1*4 + dl;
    const ulonglong2* wh2 = WH + kh*128 + 2*4 + dl;
    const ulonglong2* wh3 = WH + kh*128 + 3*4 + dl;
    const ulonglong2* wx0 = wh0 + 2048;
    const ulonglong2* wx1 = wh1 + 2048;
    const ulonglong2* wx2 = wh2 + 2048;
    const ulonglong2* wx3 = wh3 + 2048;
    const ulonglong2* hp = ((const ulonglong2*)shH) + kh * 256 + bq;
    const ulonglong2* xp = ((const ulonglong2*)shX) + kh * 256 + bq;

    // staging (warp-private 4KB slices, split into two 2KB halves)
    const unsigned stH =
        (unsigned)__cvta_generic_to_shared(shH) + (unsigned)(kh * 256 + lane) * 16u;
    const unsigned stX =
        (unsigned)__cvta_generic_to_shared(shX) + (unsigned)(kh * 256 + lane) * 16u;
    const int stg_src = kh * 256 + lane;

    // poll: producers of k-slice kh are blocks kh*8 .. kh*8+7
    // half1 = blocks kh*8+0..3 (k4 kh*8..+3); half2 = kh*8+4..7
    unsigned* pf = &g_flag[(kh * 8 + (lane & 7)) * 8];

    // reduce role: warp kh = (rg = kh>>2 gate, rd = kh&3 dim-local)
    const int rg = kh >> 2;
    const int rd = kh & 3;
    const float* rp = shR + (rg * 4 + (lane >> 3)) * 527 + rd * 8 + (lane & 7);

    // owner role (tid < 128): pb = tid&31, pd = tid>>5
    const int pb = tid & 31;
    const int pd = tid >> 5;
    const int dgp = bx * 4 + pd;
    float* outp = out + (size_t)pb * ((size_t)TT * DIM) + dgp;
    const int hwidx = bx * 128 + pb * 4 + pd;

    float cc = 0.0f;
    float hv = 0.0f;

    // prologue: stage x for t = 0
    {
        const float4* xs = (const float4*)g_xT + stg_src;
        #pragma unroll
        for (int q = 0; q < 8; q++) cpa16(stX + q * 512u, xs + q * 32);
        asm volatile("cp.async.commit_group;");
    }
    __syncthreads();                       // W + biases ready

    for (int t = 0; t < TT; t++){
        // ---- wait x(t) (staged previous iter / prologue) ----
        asm volatile("cp.async.wait_group 0;");
        __syncwarp();

        ull acc[4][4];
        #pragma unroll
        for (int g = 0; g < 4; g++)
            #pragma unroll
            for (int j = 0; j < 4; j++) acc[g][j] = 0ULL;

        // ---- x-FMA ----
        #pragma unroll
        for (int i = 0; i < 8; i++){
            ulonglong2 x0 = xp[i * 32];
            ulonglong2 x1 = xp[i * 32 + 8];
            ulonglong2 x2 = xp[i * 32 + 16];
            ulonglong2 x3 = xp[i * 32 + 24];
            ulonglong2 v0 = wx0[i * 16], v1 = wx1[i * 16];
            ulonglong2 v2 = wx2[i * 16], v3 = wx3[i * 16];
            acc[0][0]=f2fma(x0.x,v0.x,acc[0][0]); acc[0][0]=f2fma(x0.y,v0.y,acc[0][0]);
            acc[0][1]=f2fma(x1.x,v0.x,acc[0][1]); acc[0][1]=f2fma(x1.y,v0.y,acc[0][1]);
            acc[0][2]=f2fma(x2.x,v0.x,acc[0][2]); acc[0][2]=f2fma(x2.y,v0.y,acc[0][2]);
            acc[0][3]=f2fma(x3.x,v0.x,acc[0][3]); acc[0][3]=f2fma(x3.y,v0.y,acc[0][3]);
            acc[1][0]=f2fma(x0.x,v1.x,acc[1][0]); acc[1][0]=f2fma(x0.y,v1.y,acc[1][0]);
            acc[1][1]=f2fma(x1.x,v1.x,acc[1][1]); acc[1][1]=f2fma(x1.y,v1.y,acc[1][1]);
            acc[1][2]=f2fma(x2.x,v1.x,acc[1][2]); acc[1][2]=f2fma(x2.y,v1.y,acc[1][2]);
            acc[1][3]=f2fma(x3.x,v1.x,acc[1][3]); acc[1][3]=f2fma(x3.y,v1.y,acc[1][3]);
            acc[2][0]=f2fma(x0.x,v2.x,acc[2][0]); acc[2][0]=f2fma(x0.y,v2.y,acc[2][0]);
            acc[2][1]=f2fma(x1.x,v2.x,acc[2][1]); acc[2][1]=f2fma(x1.y,v2.y,acc[2][1]);
            acc[2][2]=f2fma(x2.x,v2.x,acc[2][2]); acc[2][2]=f2fma(x2.y,v2.y,acc[2][2]);
            acc[2][3]=f2fma(x3.x,v2.x,acc[2][3]); acc[2][3]=f2fma(x3.y,v2.y,acc[2][3]);
            acc[3][0]=f2fma(x0.x,v3.x,acc[3][0]); acc[3][0]=f2fma(x0.y,v3.y,acc[3][0]);
            acc[3][1]=f2fma(x1.x,v3.x,acc[3][1]); acc[3][1]=f2fma(x1.y,v3.y,acc[3][1]);
            acc[3][2]=f2fma(x2.x,v3.x,acc[3][2]); acc[3][2]=f2fma(x2.y,v3.y,acc[3][2]);
            acc[3][3]=f2fma(x3.x,v3.x,acc[3][3]); acc[3][3]=f2fma(x3.y,v3.y,acc[3][3]);
        }

        // ---- poll half1 producers, stage h half1 ----
        if (lane < 4){
            while (ld_acquire(pf) < (unsigned)t) { }
        }
        __syncwarp();
        {
            const float4* hs = (const float4*)g_hbuf[t & 3] + stg_src;
            #pragma unroll
            for (int q = 0; q < 4; q++) cpa16(stH + q * 512u, hs + q * 32);
            asm volatile("cp.async.commit_group;");      // group H1
        }

        // ---- poll half2 producers, stage h half2 ----
        if (lane >= 4 && lane < 8){
            while (ld_acquire(pf) < (unsigned)t) { }
        }
        __syncwarp();
        {
            const float4* hs = (const float4*)g_hbuf[t & 3] + stg_src + 128;
            #pragma unroll
            for (int q = 0; q < 4; q++) cpa16(stH + 2048u + q * 512u, hs + q * 32);
            asm volatile("cp.async.commit_group;");      // group H2
        }

        // ---- prefetch x(t+1), committed last ----
        {
            int tn = (t + 1 < TT) ? (t + 1) : t;
            const float4* xs = (const float4*)g_xT + (size_t)tn * 4096 + stg_src;
            #pragma unroll
            for (int q = 0; q < 8; q++) cpa16(stX + q * 512u, xs + q * 32);
            asm volatile("cp.async.commit_group;");      // group X
        }

        // ---- h-FMA half1 (H2 stage hides underneath) ----
        asm volatile("cp.async.wait_group 2;");          // H1 done
        __syncwarp();
        #pragma unroll
        for (int i = 0; i < 4; i++){
            ulonglong2 h0 = hp[i * 32];
            ulonglong2 h1 = hp[i * 32 + 8];
            ulonglong2 h2 = hp[i * 32 + 16];
            ulonglong2 h3 = hp[i * 32 + 24];
            ulonglong2 v0 = wh0[i * 16], v1 = wh1[i * 16];
            ulonglong2 v2 = wh2[i * 16], v3 = wh3[i * 16];
            acc[0][0]=f2fma(h0.x,v0.x,acc[0][0]); acc[0][0]=f2fma(h0.y,v0.y,acc[0][0]);
            acc[0][1]=f2fma(h1.x,v0.x,acc[0][1]); acc[0][1]=f2fma(h1.y,v0.y,acc[0][1]);
            acc[0][2]=f2fma(h2.x,v0.x,acc[0][2]); acc[0][2]=f2fma(h2.y,v0.y,acc[0][2]);
            acc[0][3]=f2fma(h3.x,v0.x,acc[0][3]); acc[0][3]=f2fma(h3.y,v0.y,acc[0][3]);
            acc[1][0]=f2fma(h0.x,v1.x,acc[1][0]); acc[1][0]=f2fma(h0.y,v1.y,acc[1][0]);
            acc[1][1]=f2fma(h1.x,v1.x,acc[1][1]); acc[1][1]=f2fma(h1.y,v1.y,acc[1][1]);
            acc[1][2]=f2fma(h2.x,v1.x,acc[1][2]); acc[1][2]=f2fma(h2.y,v1.y,acc[1][2]);
            acc[1][3]=f2fma(h3.x,v1.x,acc[1][3]); acc[1][3]=f2fma(h3.y,v1.y,acc[1][3]);
            acc[2][0]=f2fma(h0.x,v2.x,acc[2][0]); acc[2][0]=f2fma(h0.y,v2.y,acc[2][0]);
            acc[2][1]=f2fma(h1.x,v2.x,acc[2][1]); acc[2][1]=f2fma(h1.y,v2.y,acc[2][1]);
            acc[2][2]=f2fma(h2.x,v2.x,acc[2][2]); acc[2][2]=f2fma(h2.y,v2.y,acc[2][2]);
            acc[2][3]=f2fma(h3.x,v2.x,acc[2][3]); acc[2][3]=f2fma(h3.y,v2.y,acc[2][3]);
            acc[3][0]=f2fma(h0.x,v3.x,acc[3][0]); acc[3][0]=f2fma(h0.y,v3.y,acc[3][0]);
            acc[3][1]=f2fma(h1.x,v3.x,acc[3][1]); acc[3][1]=f2fma(h1.y,v3.y,acc[3][1]);
            acc[3][2]=f2fma(h2.x,v3.x,acc[3][2]); acc[3][2]=f2fma(h2.y,v3.y,acc[3][2]);
            acc[3][3]=f2fma(h3.x,v3.x,acc[3][3]); acc[3][3]=f2fma(h3.y,v3.y,acc[3][3]);
        }

        // ---- h-FMA half2 ----
        asm volatile("cp.async.wait_group 1;");          // H2 done (X pending)
        __syncwarp();
        #pragma unroll
        for (int i = 4; i < 8; i++){
            ulonglong2 h0 = hp[i * 32];
            ulonglong2 h1 = hp[i * 32 + 8];
            ulonglong2 h2 = hp[i * 32 + 16];
            ulonglong2 h3 = hp[i * 32 + 24];
            ulonglong2 v0 = wh0[i * 16], v1 = wh1[i * 16];
            ulonglong2 v2 = wh2[i * 16], v3 = wh3[i * 16];
            acc[0][0]=f2fma(h0.x,v0.x,acc[0][0]); acc[0][0]=f2fma(h0.y,v0.y,acc[0][0]);
            acc[0][1]=f2fma(h1.x,v0.x,acc[0][1]); acc[0][1]=f2fma(h1.y,v0.y,acc[0][1]);
            acc[0][2]=f2fma(h2.x,v0.x,acc[0][2]); acc[0][2]=f2fma(h2.y,v0.y,acc[0][2]);
            acc[0][3]=f2fma(h3.x,v0.x,acc[0][3]); acc[0][3]=f2fma(h3.y,v0.y,acc[0][3]);
            acc[1][0]=f2fma(h0.x,v1.x,acc[1][0]); acc[1][0]=f2fma(h0.y,v1.y,acc[1][0]);
            acc[1][1]=f2fma(h1.x,v1.x,acc[1][1]); acc[1][1]=f2fma(h1.y,v1.y,acc[1][1]);
            acc[1][2]=f2fma(h2.x,v1.x,acc[1][2]); acc[1][2]=f2fma(h2.y,v1.y,acc[1][2]);
            acc[1][3]=f2fma(h3.x,v1.x,acc[1][3]); acc[1][3]=f2fma(h3.y,v1.y,acc[1][3]);
            acc[2][0]=f2fma(h0.x,v2.x,acc[2][0]); acc[2][0]=f2fma(h0.y,v2.y,acc[2][0]);
            acc[2][1]=f2fma(h1.x,v2.x,acc[2][1]); acc[2][1]=f2fma(h1.y,v2.y,acc[2][1]);
            acc[2][2]=f2fma(h2.x,v2.x,acc[2][2]); acc[2][2]=f2fma(h2.y,v2.y,acc[2][2]);
            acc[2][3]=f2fma(h3.x,v2.x,acc[2][3]); acc[2][3]=f2fma(h3.y,v2.y,acc[2][3]);
            acc[3][0]=f2fma(h0.x,v3.x,acc[3][0]); acc[3][0]=f2fma(h0.y,v3.y,acc[3][0]);
            acc[3][1]=f2fma(h1.x,v3.x,acc[3][1]); acc[3][1]=f2fma(h1.y,v3.y,acc[3][1]);
            acc[3][2]=f2fma(h2.x,v3.x,acc[3][2]); acc[3][2]=f2fma(h2.y,v3.y,acc[3][2]);
            acc[3][3]=f2fma(h3.x,v3.x,acc[3][3]); acc[3][3]=f2fma(h3.y,v3.y,acc[3][3]);
        }

        // ---- partials: shR[(g*4+j)*527 + kh*33 + lane] ----
        #pragma unroll
        for (int g = 0; g < 4; g++)
            #pragma unroll
            for (int j = 0; j < 4; j++)
                shR[(g*4 + j) * 527 + kh * 33 + lane] = hadd(acc[g][j]);
        __syncthreads();                   // bar1: all partials in

        // ---- reduce (warp = gate x dim, lane = batch) + bias + nonlin ----
        {
            float s = shB[rg * 4 + rd];
            #pragma unroll
            for (int k = 0; k < 16; k++) s += rp[k * 33];
            shG[rg * 128 + rd * 32 + lane] = (rg == 2) ? tanhfast(s) : sigf(s);
        }
        __syncthreads();                   // bar2: gates ready

        // ---- owners: c/h update, named bar, early release ----
        if (tid < 128){
            float iv = shG[  0 + pd * 32 + pb];
            float fv = shG[128 + pd * 32 + pb];
            float gv = shG[256 + pd * 32 + pb];
            float ov = shG[384 + pd * 32 + pb];
            cc = fv * cc + iv * gv;
            hv = ov * tanhfast(cc);
            g_hbuf[(t + 1) & 3][hwidx] = hv;
            asm volatile("bar.sync 3, 128;");            // owners only
            if (tid == 0 && t + 1 < TT)
                st_release(&g_flag[bx * 8], (unsigned)(t + 1));
            outp[(size_t)t * DIM] = hv;                  // off the release path
        }
        // warps 4-15 proceed directly to step t+1 (ring safe: every
        // block's poll set covers all 128 flags -> 1-hop transitivity)
    }
}

// =====================================================================
extern "C" void kernel_launch(void* const* d_in, const int* in_sizes, int n_in,
                              void* d_out, int out_size)
{
    (void)in_sizes; (void)n_in; (void)out_size;
    const float* x    = (const float*)d_in[0];
    const float* Wih  = (const float*)d_in[1];
    const float* Whh  = (const float*)d_in[2];
    const float* bih  = (const float*)d_in[3];
    const float* bhh  = (const float*)d_in[4];
    float* out = (float*)d_out;

    // 16384 + 16384 + 16384 + 8432 + 512 + 16 = 58112 floats = 232448 bytes
    cudaFuncSetAttribute(lstm_rec_kernel,
                         cudaFuncAttributeMaxDynamicSharedMemorySize, 232448);

    xt_kernel<<<(TT * DIM * BATCH / 4) / 256, 256>>>(x);
    lstm_rec_kernel<<<NBLK, RTHR, 232448>>>(Wih, Whh, bih, bhh, out);
}

// round 16
// speedup vs baseline: 1.2259x; 1.0556x over previous
#include <cuda_runtime.h>
#include <cstdint>

#define DIM   512
#define BATCH 32
#define TT    2048
#define NBLK  128
#define RTHR  512

// ---------------- device scratch (no allocations allowed) ----------------
__device__ __align__(16) float g_xT[(size_t)TT * DIM * BATCH];  // [t][k4][b][4]
__device__ __align__(16) float g_hbuf[TT + 1][DIM * BATCH];     // full h history
__device__ unsigned g_flag[NBLK * 8];   // one flag per block, 32B apart

typedef unsigned long long ull;

// ---------------- f32x2 helpers ----------------
__device__ __forceinline__ ull f2fma(ull a, ull b, ull c){
    ull d; asm("fma.rn.f32x2 %0, %1, %2, %3;" : "=l"(d) : "l"(a), "l"(b), "l"(c)); return d;
}
__device__ __forceinline__ float2 upk(ull v){
    float2 f; asm("mov.b64 {%0, %1}, %2;" : "=f"(f.x), "=f"(f.y) : "l"(v)); return f;
}
__device__ __forceinline__ float hadd(ull v){ float2 f = upk(v); return f.x + f.y; }

__device__ __forceinline__ float sigf(float x){ return 1.0f / (1.0f + __expf(-x)); }
__device__ __forceinline__ float tanhfast(float x){
    float e = __expf(2.0f * x);              // inf-safe at both ends
    return 1.0f - 2.0f / (e + 1.0f);
}

// ---------------- scoped sync primitives ----------------
__device__ __forceinline__ void st_release(unsigned* p, unsigned v){
    asm volatile("st.release.gpu.global.u32 [%0], %1;" :: "l"(p), "r"(v) : "memory");
}
__device__ __forceinline__ unsigned ld_acquire(unsigned* p){
    unsigned v;
    asm volatile("ld.acquire.gpu.global.u32 %0, [%1];" : "=r"(v) : "l"(p) : "memory");
    return v;
}
__device__ __forceinline__ void cpa16(unsigned dst, const void* src){
    asm volatile("cp.async.cg.shared.global [%0], [%1], 16;" :: "r"(dst), "l"(src));
}

// =====================================================================
// Kernel 1: transpose x[b][t][k] -> xT[t][k4][b][4]; block 0 inits state.
// =====================================================================
__global__ void __launch_bounds__(256) xt_kernel(const float* __restrict__ x)
{
    if (blockIdx.x == 0){
        int tid = threadIdx.x;
        for (int i = tid; i < DIM * BATCH; i += 256) g_hbuf[0][i] = 0.0f;
        for (int i = tid; i < NBLK; i += 256) g_flag[i * 8] = 0u;
    }
    size_t gidx = (size_t)blockIdx.x * 256 + threadIdx.x;
    int b  = (int)(gidx & 31);
    int k4 = (int)((gidx >> 5) & 127);
    int t  = (int)(gidx >> 12);
    float4 v = *(const float4*)(x + (size_t)b * ((size_t)TT * DIM)
                                  + (size_t)t * DIM + k4 * 4);
    ((float4*)g_xT)[gidx] = v;
}

// =====================================================================
// Kernel 3: out[b][t][d] <- g_hbuf[t+1][(d>>2)*128 + b*4 + (d&3)].
// Thread = one float4 of out (4 consecutive d); both sides 16B.
// =====================================================================
__global__ void __launch_bounds__(256) out_kernel(float* __restrict__ out)
{
    size_t gidx = (size_t)blockIdx.x * 256 + threadIdx.x;   // [b][t][d4]
    int d4 = (int)(gidx & 127);
    int t  = (int)((gidx >> 7) & 2047);
    int b  = (int)(gidx >> 18);
    float4 v = *(const float4*)&g_hbuf[t + 1][d4 * 128 + b * 4];
    ((float4*)out)[gidx] = v;
}

// =====================================================================
// Kernel 2: fused persistent LSTM (R11 base; h written to full history
// buffer -> no per-step out store, no ring/WAR bookkeeping).
// 128 blocks x 512 threads; warp kh owns k-slice [kh*32,+32);
// lane = (bq = l&7, dl = l>>3); 4 gates x 4 batches x dim bx*4+dl,
// x-part + h-part into same acc. Per-warp poll of 8 producer flags;
// warp-private 4KB cp.async staging; shR stride 527; reduce warp =
// (gate, dim); owners tid<128 c/h update + coalesced h store.
// =====================================================================
__global__ void __launch_bounds__(RTHR) lstm_rec_kernel(
    const float* __restrict__ Wih, const float* __restrict__ Whh,
    const float* __restrict__ bih, const float* __restrict__ bhh)
{
    extern __shared__ float sm[];
    float* shW = sm;              // 16384 fl: f4 idx k4*16+rl ; +2048 f4 = Wih
    float* shH = sm + 16384;      // 16384 fl: [k4][b][4]
    float* shX = sm + 32768;      // 16384 fl: [k4][b][4]
    float* shR = sm + 49152;      // 16 rows x 527
    float* shG = sm + 57584;      // 512 gate values [g*128 + d*32 + b]
    float* shB = sm + 58096;      // 16 biases

    const int tid  = threadIdx.x;
    const int bx   = blockIdx.x;
    const int kh   = tid >> 5;
    const int lane = tid & 31;
    const int bq   = lane & 7;
    const int dl   = lane >> 3;

    // Load W_hh and W_ih slices into [k4][rl] layout (once).
    for (int idx = tid; idx < 4096; idx += RTHR){
        int half = idx >> 11;              // 0 = hh, 1 = ih
        int rem  = idx & 2047;
        int rl   = rem >> 7;               // g*4 + dloc
        int k4   = rem & 127;
        int g = rl >> 2, dloc = rl & 3;
        const float* src = (half ? Wih : Whh)
                         + (size_t)(g * DIM + bx * 4 + dloc) * DIM + k4 * 4;
        ((float4*)shW)[half * 2048 + k4 * 16 + rl] = *(const float4*)src;
    }
    if (tid < 16){
        int n = (tid >> 2) * DIM + bx * 4 + (tid & 3);
        shB[tid] = bih[n] + bhh[n];
    }

    // FMA pointers: f4 idx = (kh*8+i)*16 + g*4 + dl
    const ulonglong2* WH = (const ulonglong2*)shW;
    const ulonglong2* wh0 = WH + kh*128 + 0*4 + dl;
    const ulonglong2* wh1 = WH + kh*128 + 1*4 + dl;
    const ulonglong2* wh2 = WH + kh*128 + 2*4 + dl;
    const ulonglong2* wh3 = WH + kh*128 + 3*4 + dl;
    const ulonglong2* wx0 = wh0 + 2048;
    const ulonglong2* wx1 = wh1 + 2048;
    const ulonglong2* wx2 = wh2 + 2048;
    const ulonglong2* wx3 = wh3 + 2048;
    const ulonglong2* hp = ((const ulonglong2*)shH) + kh * 256 + bq;
    const ulonglong2* xp = ((const ulonglong2*)shX) + kh * 256 + bq;

    // staging (warp-private 4KB slices)
    const unsigned stH =
        (unsigned)__cvta_generic_to_shared(shH) + (unsigned)(kh * 256 + lane) * 16u;
    const unsigned stX =
        (unsigned)__cvta_generic_to_shared(shX) + (unsigned)(kh * 256 + lane) * 16u;
    const int stg_src = kh * 256 + lane;

    // poll: producers of k-slice kh are blocks kh*8 .. kh*8+7
    unsigned* pf = &g_flag[(kh * 8 + (lane & 7)) * 8];

    // reduce role: warp kh = (rg = kh>>2 gate, rd = kh&3 dim-local)
    const int rg = kh >> 2;
    const int rd = kh & 3;
    const float* rp = shR + (rg * 4 + (lane >> 3)) * 527 + rd * 8 + (lane & 7);

    // owner role (tid < 128): pb = tid&31, pd = tid>>5
    const int pb = tid & 31;
    const int pd = tid >> 5;
    const int hwidx = bx * 128 + pb * 4 + pd;     // [k4][b][4] flat index

    float cc = 0.0f;

    // prologue: stage x for t = 0
    {
        const float4* xs = (const float4*)g_xT + stg_src;
        #pragma unroll
        for (int q = 0; q < 8; q++) cpa16(stX + q * 512u, xs + q * 32);
        asm volatile("cp.async.commit_group;");
    }
    __syncthreads();                       // W + biases ready

    for (int t = 0; t < TT; t++){
        asm volatile("cp.async.wait_group 0;");
        __syncwarp();

        ull acc[4][4];
        #pragma unroll
        for (int g = 0; g < 4; g++)
            #pragma unroll
            for (int j = 0; j < 4; j++) acc[g][j] = 0ULL;

        // ---- x-FMA ----
        #pragma unroll
        for (int i = 0; i < 8; i++){
            ulonglong2 x0 = xp[i * 32];
            ulonglong2 x1 = xp[i * 32 + 8];
            ulonglong2 x2 = xp[i * 32 + 16];
            ulonglong2 x3 = xp[i * 32 + 24];
            ulonglong2 v0 = wx0[i * 16], v1 = wx1[i * 16];
            ulonglong2 v2 = wx2[i * 16], v3 = wx3[i * 16];
            acc[0][0]=f2fma(x0.x,v0.x,acc[0][0]); acc[0][0]=f2fma(x0.y,v0.y,acc[0][0]);
            acc[0][1]=f2fma(x1.x,v0.x,acc[0][1]); acc[0][1]=f2fma(x1.y,v0.y,acc[0][1]);
            acc[0][2]=f2fma(x2.x,v0.x,acc[0][2]); acc[0][2]=f2fma(x2.y,v0.y,acc[0][2]);
            acc[0][3]=f2fma(x3.x,v0.x,acc[0][3]); acc[0][3]=f2fma(x3.y,v0.y,acc[0][3]);
            acc[1][0]=f2fma(x0.x,v1.x,acc[1][0]); acc[1][0]=f2fma(x0.y,v1.y,acc[1][0]);
            acc[1][1]=f2fma(x1.x,v1.x,acc[1][1]); acc[1][1]=f2fma(x1.y,v1.y,acc[1][1]);
            acc[1][2]=f2fma(x2.x,v1.x,acc[1][2]); acc[1][2]=f2fma(x2.y,v1.y,acc[1][2]);
            acc[1][3]=f2fma(x3.x,v1.x,acc[1][3]); acc[1][3]=f2fma(x3.y,v1.y,acc[1][3]);
            acc[2][0]=f2fma(x0.x,v2.x,acc[2][0]); acc[2][0]=f2fma(x0.y,v2.y,acc[2][0]);
            acc[2][1]=f2fma(x1.x,v2.x,acc[2][1]); acc[2][1]=f2fma(x1.y,v2.y,acc[2][1]);
            acc[2][2]=f2fma(x2.x,v2.x,acc[2][2]); acc[2][2]=f2fma(x2.y,v2.y,acc[2][2]);
            acc[2][3]=f2fma(x3.x,v2.x,acc[2][3]); acc[2][3]=f2fma(x3.y,v2.y,acc[2][3]);
            acc[3][0]=f2fma(x0.x,v3.x,acc[3][0]); acc[3][0]=f2fma(x0.y,v3.y,acc[3][0]);
            acc[3][1]=f2fma(x1.x,v3.x,acc[3][1]); acc[3][1]=f2fma(x1.y,v3.y,acc[3][1]);
            acc[3][2]=f2fma(x2.x,v3.x,acc[3][2]); acc[3][2]=f2fma(x2.y,v3.y,acc[3][2]);
            acc[3][3]=f2fma(x3.x,v3.x,acc[3][3]); acc[3][3]=f2fma(x3.y,v3.y,acc[3][3]);
        }

        // ---- prefetch x for t+1 ----
        {
            int tn = (t + 1 < TT) ? (t + 1) : t;
            const float4* xs = (const float4*)g_xT + (size_t)tn * 4096 + stg_src;
            #pragma unroll
            for (int q = 0; q < 8; q++) cpa16(stX + q * 512u, xs + q * 32);
            asm volatile("cp.async.commit_group;");
        }

        // ---- poll my 8 producers, stage h ----
        if (lane < 8){
            while (ld_acquire(pf) < (unsigned)t) { }
        }
        __syncwarp();
        {
            const float4* hs = (const float4*)g_hbuf[t] + stg_src;
            #pragma unroll
            for (int q = 0; q < 8; q++) cpa16(stH + q * 512u, hs + q * 32);
            asm volatile("cp.async.commit_group;");
            asm volatile("cp.async.wait_group 0;");
        }
        __syncwarp();

        // ---- h-FMA into same accumulators ----
        #pragma unroll
        for (int i = 0; i < 8; i++){
            ulonglong2 h0 = hp[i * 32];
            ulonglong2 h1 = hp[i * 32 + 8];
            ulonglong2 h2 = hp[i * 32 + 16];
            ulonglong2 h3 = hp[i * 32 + 24];
            ulonglong2 v0 = wh0[i * 16], v1 = wh1[i * 16];
            ulonglong2 v2 = wh2[i * 16], v3 = wh3[i * 16];
            acc[0][0]=f2fma(h0.x,v0.x,acc[0][0]); acc[0][0]=f2fma(h0.y,v0.y,acc[0][0]);
            acc[0][1]=f2fma(h1.x,v0.x,acc[0][1]); acc[0][1]=f2fma(h1.y,v0.y,acc[0][1]);
            acc[0][2]=f2fma(h2.x,v0.x,acc[0][2]); acc[0][2]=f2fma(h2.y,v0.y,acc[0][2]);
            acc[0][3]=f2fma(h3.x,v0.x,acc[0][3]); acc[0][3]=f2fma(h3.y,v0.y,acc[0][3]);
            acc[1][0]=f2fma(h0.x,v1.x,acc[1][0]); acc[1][0]=f2fma(h0.y,v1.y,acc[1][0]);
            acc[1][1]=f2fma(h1.x,v1.x,acc[1][1]); acc[1][1]=f2fma(h1.y,v1.y,acc[1][1]);
            acc[1][2]=f2fma(h2.x,v1.x,acc[1][2]); acc[1][2]=f2fma(h2.y,v1.y,acc[1][2]);
            acc[1][3]=f2fma(h3.x,v1.x,acc[1][3]); acc[1][3]=f2fma(h3.y,v1.y,acc[1][3]);
            acc[2][0]=f2fma(h0.x,v2.x,acc[2][0]); acc[2][0]=f2fma(h0.y,v2.y,acc[2][0]);
            acc[2][1]=f2fma(h1.x,v2.x,acc[2][1]); acc[2][1]=f2fma(h1.y,v2.y,acc[2][1]);
            acc[2][2]=f2fma(h2.x,v2.x,acc[2][2]); acc[2][2]=f2fma(h2.y,v2.y,acc[2][2]);
            acc[2][3]=f2fma(h3.x,v2.x,acc[2][3]); acc[2][3]=f2fma(h3.y,v2.y,acc[2][3]);
            acc[3][0]=f2fma(h0.x,v3.x,acc[3][0]); acc[3][0]=f2fma(h0.y,v3.y,acc[3][0]);
            acc[3][1]=f2fma(h1.x,v3.x,acc[3][1]); acc[3][1]=f2fma(h1.y,v3.y,acc[3][1]);
            acc[3][2]=f2fma(h2.x,v3.x,acc[3][2]); acc[3][2]=f2fma(h2.y,v3.y,acc[3][2]);
            acc[3][3]=f2fma(h3.x,v3.x,acc[3][3]); acc[3][3]=f2fma(h3.y,v3.y,acc[3][3]);
        }

        // ---- partials: shR[(g*4+j)*527 + kh*33 + lane] ----
        #pragma unroll
        for (int g = 0; g < 4; g++)
            #pragma unroll
            for (int j = 0; j < 4; j++)
                shR[(g*4 + j) * 527 + kh * 33 + lane] = hadd(acc[g][j]);
        __syncthreads();                   // bar1: all partials in

        // ---- reduce (warp = gate x dim, lane = batch) + bias + nonlin ----
        {
            float s = shB[rg * 4 + rd];
            #pragma unroll
            for (int k = 0; k < 16; k++) s += rp[k * 33];
            shG[rg * 128 + rd * 32 + lane] = (rg == 2) ? tanhfast(s) : sigf(s);
        }
        __syncthreads();                   // bar2: gates ready

        // ---- owners: c/h update, coalesced h store (the ONLY gmem write) ----
        if (tid < 128){
            float iv = shG[  0 + pd * 32 + pb];
            float fv = shG[128 + pd * 32 + pb];
            float gv = shG[256 + pd * 32 + pb];
            float ov = shG[384 + pd * 32 + pb];
            cc = fv * cc + iv * gv;
            float hv = ov * tanhfast(cc);
            g_hbuf[t + 1][hwidx] = hv;
        }
        __syncthreads();                   // bar3: h stores done block-wide

        if (t + 1 < TT){
            if (tid == 0) st_release(&g_flag[bx * 8], (unsigned)(t + 1));
        }
    }
}

// =====================================================================
extern "C" void kernel_launch(void* const* d_in, const int* in_sizes, int n_in,
                              void* d_out, int out_size)
{
    (void)in_sizes; (void)n_in; (void)out_size;
    const float* x    = (const float*)d_in[0];
    const float* Wih  = (const float*)d_in[1];
    const float* Whh  = (const float*)d_in[2];
    const float* bih  = (const float*)d_in[3];
    const float* bhh  = (const float*)d_in[4];
    float* out = (float*)d_out;

    // 16384 + 16384 + 16384 + 8432 + 512 + 16 = 58112 floats = 232448 bytes
    cudaFuncSetAttribute(lstm_rec_kernel,
                         cudaFuncAttributeMaxDynamicSharedMemorySize, 232448);

    xt_kernel<<<(TT * DIM * BATCH / 4) / 256, 256>>>(x);
    lstm_rec_kernel<<<NBLK, RTHR, 232448>>>(Wih, Whh, bih, bhh);
    out_kernel<<<(BATCH * TT * DIM / 4) / 256, 256>>>(out);
}

// round 17
// speedup vs baseline: 1.2331x; 1.0059x over previous
#include <cuda_runtime.h>
#include <cstdint>

#define DIM   512
#define BATCH 32
#define TT    2048
#define NBLK  128
#define RTHR  512

// ---------------- device scratch (no allocations allowed) ----------------
__device__ __align__(16) float g_xT[(size_t)TT * DIM * BATCH];  // [t][k4][b][4]
__device__ __align__(16) float g_hbuf[TT + 1][DIM * BATCH];     // full h history
__device__ unsigned g_flag[NBLK * 8];   // one flag per block, 32B apart

typedef unsigned long long ull;

// ---------------- f32x2 helpers ----------------
__device__ __forceinline__ ull f2fma(ull a, ull b, ull c){
    ull d; asm("fma.rn.f32x2 %0, %1, %2, %3;" : "=l"(d) : "l"(a), "l"(b), "l"(c)); return d;
}
__device__ __forceinline__ float2 upk(ull v){
    float2 f; asm("mov.b64 {%0, %1}, %2;" : "=f"(f.x), "=f"(f.y) : "l"(v)); return f;
}
__device__ __forceinline__ float hadd(ull v){ float2 f = upk(v); return f.x + f.y; }

__device__ __forceinline__ float sigf(float x){ return 1.0f / (1.0f + __expf(-x)); }
__device__ __forceinline__ float tanhfast(float x){
    float e = __expf(2.0f * x);              // inf-safe at both ends
    return 1.0f - 2.0f / (e + 1.0f);
}

// ---------------- scoped sync primitives ----------------
__device__ __forceinline__ void st_release(unsigned* p, unsigned v){
    asm volatile("st.release.gpu.global.u32 [%0], %1;" :: "l"(p), "r"(v) : "memory");
}
__device__ __forceinline__ unsigned ld_acquire(unsigned* p){
    unsigned v;
    asm volatile("ld.acquire.gpu.global.u32 %0, [%1];" : "=r"(v) : "l"(p) : "memory");
    return v;
}
__device__ __forceinline__ void cpa16(unsigned dst, const void* src){
    asm volatile("cp.async.cg.shared.global [%0], [%1], 16;" :: "r"(dst), "l"(src));
}

// =====================================================================
// Kernel 1: transpose x[b][t][k] -> xT[t][k4][b][4]; block 0 inits state.
// =====================================================================
__global__ void __launch_bounds__(256) xt_kernel(const float* __restrict__ x)
{
    if (blockIdx.x == 0){
        int tid = threadIdx.x;
        for (int i = tid; i < DIM * BATCH; i += 256) g_hbuf[0][i] = 0.0f;
        for (int i = tid; i < NBLK; i += 256) g_flag[i * 8] = 0u;
    }
    size_t gidx = (size_t)blockIdx.x * 256 + threadIdx.x;
    int b  = (int)(gidx & 31);
    int k4 = (int)((gidx >> 5) & 127);
    int t  = (int)(gidx >> 12);
    float4 v = *(const float4*)(x + (size_t)b * ((size_t)TT * DIM)
                                  + (size_t)t * DIM + k4 * 4);
    ((float4*)g_xT)[gidx] = v;
}

// =====================================================================
// Kernel 3: out[b][t][d] <- g_hbuf[t+1][(d>>2)*128 + b*4 + (d&3)].
// =====================================================================
__global__ void __launch_bounds__(256) out_kernel(float* __restrict__ out)
{
    size_t gidx = (size_t)blockIdx.x * 256 + threadIdx.x;   // [b][t][d4]
    int d4 = (int)(gidx & 127);
    int t  = (int)((gidx >> 7) & 2047);
    int b  = (int)(gidx >> 18);
    float4 v = *(const float4*)&g_hbuf[t + 1][d4 * 128 + b * 4];
    ((float4*)out)[gidx] = v;
}

// =====================================================================
// Kernel 2: fused persistent LSTM (R16 base; block-wide bar3 replaced
// by owners-only bar.sync 3,128 -> warps 4-15 start step t+1 during
// the owner tail + release propagation).
// 128 blocks x 512 threads; warp kh owns k-slice [kh*32,+32);
// lane = (bq = l&7, dl = l>>3); 4 gates x 4 batches x dim bx*4+dl,
// x-part + h-part into same acc. Per-warp poll of 8 producer flags;
// warp-private 4KB cp.async staging; shR stride 527; reduce warp =
// (gate, dim); owners tid<128 (= warps 0-3 exactly).
// =====================================================================
__global__ void __launch_bounds__(RTHR) lstm_rec_kernel(
    const float* __restrict__ Wih, const float* __restrict__ Whh,
    const float* __restrict__ bih, const float* __restrict__ bhh)
{
    extern __shared__ float sm[];
    float* shW = sm;              // 16384 fl: f4 idx k4*16+rl ; +2048 f4 = Wih
    float* shH = sm + 16384;      // 16384 fl: [k4][b][4]
    float* shX = sm + 32768;      // 16384 fl: [k4][b][4]
    float* shR = sm + 49152;      // 16 rows x 527
    float* shG = sm + 57584;      // 512 gate values [g*128 + d*32 + b]
    float* shB = sm + 58096;      // 16 biases

    const int tid  = threadIdx.x;
    const int bx   = blockIdx.x;
    const int kh   = tid >> 5;
    const int lane = tid & 31;
    const int bq   = lane & 7;
    const int dl   = lane >> 3;

    // Load W_hh and W_ih slices into [k4][rl] layout (once).
    for (int idx = tid; idx < 4096; idx += RTHR){
        int half = idx >> 11;              // 0 = hh, 1 = ih
        int rem  = idx & 2047;
        int rl   = rem >> 7;               // g*4 + dloc
        int k4   = rem & 127;
        int g = rl >> 2, dloc = rl & 3;
        const float* src = (half ? Wih : Whh)
                         + (size_t)(g * DIM + bx * 4 + dloc) * DIM + k4 * 4;
        ((float4*)shW)[half * 2048 + k4 * 16 + rl] = *(const float4*)src;
    }
    if (tid < 16){
        int n = (tid >> 2) * DIM + bx * 4 + (tid & 3);
        shB[tid] = bih[n] + bhh[n];
    }

    // FMA pointers: f4 idx = (kh*8+i)*16 + g*4 + dl
    const ulonglong2* WH = (const ulonglong2*)shW;
    const ulonglong2* wh0 = WH + kh*128 + 0*4 + dl;
    const ulonglong2* wh1 = WH + kh*128 + 1*4 + dl;
    const ulonglong2* wh2 = WH + kh*128 + 2*4 + dl;
    const ulonglong2* wh3 = WH + kh*128 + 3*4 + dl;
    const ulonglong2* wx0 = wh0 + 2048;
    const ulonglong2* wx1 = wh1 + 2048;
    const ulonglong2* wx2 = wh2 + 2048;
    const ulonglong2* wx3 = wh3 + 2048;
    const ulonglong2* hp = ((const ulonglong2*)shH) + kh * 256 + bq;
    const ulonglong2* xp = ((const ulonglong2*)shX) + kh * 256 + bq;

    // staging (warp-private 4KB slices)
    const unsigned stH =
        (unsigned)__cvta_generic_to_shared(shH) + (unsigned)(kh * 256 + lane) * 16u;
    const unsigned stX =
        (unsigned)__cvta_generic_to_shared(shX) + (unsigned)(kh * 256 + lane) * 16u;
    const int stg_src = kh * 256 + lane;

    // poll: producers of k-slice kh are blocks kh*8 .. kh*8+7
    unsigned* pf = &g_flag[(kh * 8 + (lane & 7)) * 8];

    // reduce role: warp kh = (rg = kh>>2 gate, rd = kh&3 dim-local)
    const int rg = kh >> 2;
    const int rd = kh & 3;
    const float* rp = shR + (rg * 4 + (lane >> 3)) * 527 + rd * 8 + (lane & 7);

    // owner role (tid < 128): pb = tid&31, pd = tid>>5
    const int pb = tid & 31;
    const int pd = tid >> 5;
    const int hwidx = bx * 128 + pb * 4 + pd;     // [k4][b][4] flat index

    float cc = 0.0f;

    // prologue: stage x for t = 0
    {
        const float4* xs = (const float4*)g_xT + stg_src;
        #pragma unroll
        for (int q = 0; q < 8; q++) cpa16(stX + q * 512u, xs + q * 32);
        asm volatile("cp.async.commit_group;");
    }
    __syncthreads();                       // W + biases ready

    for (int t = 0; t < TT; t++){
        asm volatile("cp.async.wait_group 0;");
        __syncwarp();

        ull acc[4][4];
        #pragma unroll
        for (int g = 0; g < 4; g++)
            #pragma unroll
            for (int j = 0; j < 4; j++) acc[g][j] = 0ULL;

        // ---- x-FMA ----
        #pragma unroll
        for (int i = 0; i < 8; i++){
            ulonglong2 x0 = xp[i * 32];
            ulonglong2 x1 = xp[i * 32 + 8];
            ulonglong2 x2 = xp[i * 32 + 16];
            ulonglong2 x3 = xp[i * 32 + 24];
            ulonglong2 v0 = wx0[i * 16], v1 = wx1[i * 16];
            ulonglong2 v2 = wx2[i * 16], v3 = wx3[i * 16];
            acc[0][0]=f2fma(x0.x,v0.x,acc[0][0]); acc[0][0]=f2fma(x0.y,v0.y,acc[0][0]);
            acc[0][1]=f2fma(x1.x,v0.x,acc[0][1]); acc[0][1]=f2fma(x1.y,v0.y,acc[0][1]);
            acc[0][2]=f2fma(x2.x,v0.x,acc[0][2]); acc[0][2]=f2fma(x2.y,v0.y,acc[0][2]);
            acc[0][3]=f2fma(x3.x,v0.x,acc[0][3]); acc[0][3]=f2fma(x3.y,v0.y,acc[0][3]);
            acc[1][0]=f2fma(x0.x,v1.x,acc[1][0]); acc[1][0]=f2fma(x0.y,v1.y,acc[1][0]);
            acc[1][1]=f2fma(x1.x,v1.x,acc[1][1]); acc[1][1]=f2fma(x1.y,v1.y,acc[1][1]);
            acc[1][2]=f2fma(x2.x,v1.x,acc[1][2]); acc[1][2]=f2fma(x2.y,v1.y,acc[1][2]);
            acc[1][3]=f2fma(x3.x,v1.x,acc[1][3]); acc[1][3]=f2fma(x3.y,v1.y,acc[1][3]);
            acc[2][0]=f2fma(x0.x,v2.x,acc[2][0]); acc[2][0]=f2fma(x0.y,v2.y,acc[2][0]);
            acc[2][1]=f2fma(x1.x,v2.x,acc[2][1]); acc[2][1]=f2fma(x1.y,v2.y,acc[2][1]);
            acc[2][2]=f2fma(x2.x,v2.x,acc[2][2]); acc[2][2]=f2fma(x2.y,v2.y,acc[2][2]);
            acc[2][3]=f2fma(x3.x,v2.x,acc[2][3]); acc[2][3]=f2fma(x3.y,v2.y,acc[2][3]);
            acc[3][0]=f2fma(x0.x,v3.x,acc[3][0]); acc[3][0]=f2fma(x0.y,v3.y,acc[3][0]);
            acc[3][1]=f2fma(x1.x,v3.x,acc[3][1]); acc[3][1]=f2fma(x1.y,v3.y,acc[3][1]);
            acc[3][2]=f2fma(x2.x,v3.x,acc[3][2]); acc[3][2]=f2fma(x2.y,v3.y,acc[3][2]);
            acc[3][3]=f2fma(x3.x,v3.x,acc[3][3]); acc[3][3]=f2fma(x3.y,v3.y,acc[3][3]);
        }

        // ---- prefetch x for t+1 ----
        {
            int tn = (t + 1 < TT) ? (t + 1) : t;
            const float4* xs = (const float4*)g_xT + (size_t)tn * 4096 + stg_src;
            #pragma unroll
            for (int q = 0; q < 8; q++) cpa16(stX + q * 512u, xs + q * 32);
            asm volatile("cp.async.commit_group;");
        }

        // ---- poll my 8 producers, stage h ----
        if (lane < 8){
            while (ld_acquire(pf) < (unsigned)t) { }
        }
        __syncwarp();
        {
            const float4* hs = (const float4*)g_hbuf[t] + stg_src;
            #pragma unroll
            for (int q = 0; q < 8; q++) cpa16(stH + q * 512u, hs + q * 32);
            asm volatile("cp.async.commit_group;");
            asm volatile("cp.async.wait_group 0;");
        }
        __syncwarp();

        // ---- h-FMA into same accumulators ----
        #pragma unroll
        for (int i = 0; i < 8; i++){
            ulonglong2 h0 = hp[i * 32];
            ulonglong2 h1 = hp[i * 32 + 8];
            ulonglong2 h2 = hp[i * 32 + 16];
            ulonglong2 h3 = hp[i * 32 + 24];
            ulonglong2 v0 = wh0[i * 16], v1 = wh1[i * 16];
            ulonglong2 v2 = wh2[i * 16], v3 = wh3[i * 16];
            acc[0][0]=f2fma(h0.x,v0.x,acc[0][0]); acc[0][0]=f2fma(h0.y,v0.y,acc[0][0]);
            acc[0][1]=f2fma(h1.x,v0.x,acc[0][1]); acc[0][1]=f2fma(h1.y,v0.y,acc[0][1]);
            acc[0][2]=f2fma(h2.x,v0.x,acc[0][2]); acc[0][2]=f2fma(h2.y,v0.y,acc[0][2]);
            acc[0][3]=f2fma(h3.x,v0.x,acc[0][3]); acc[0][3]=f2fma(h3.y,v0.y,acc[0][3]);
            acc[1][0]=f2fma(h0.x,v1.x,acc[1][0]); acc[1][0]=f2fma(h0.y,v1.y,acc[1][0]);
            acc[1][1]=f2fma(h1.x,v1.x,acc[1][1]); acc[1][1]=f2fma(h1.y,v1.y,acc[1][1]);
            acc[1][2]=f2fma(h2.x,v1.x,acc[1][2]); acc[1][2]=f2fma(h2.y,v1.y,acc[1][2]);
            acc[1][3]=f2fma(h3.x,v1.x,acc[1][3]); acc[1][3]=f2fma(h3.y,v1.y,acc[1][3]);
            acc[2][0]=f2fma(h0.x,v2.x,acc[2][0]); acc[2][0]=f2fma(h0.y,v2.y,acc[2][0]);
            acc[2][1]=f2fma(h1.x,v2.x,acc[2][1]); acc[2][1]=f2fma(h1.y,v2.y,acc[2][1]);
            acc[2][2]=f2fma(h2.x,v2.x,acc[2][2]); acc[2][2]=f2fma(h2.y,v2.y,acc[2][2]);
            acc[2][3]=f2fma(h3.x,v2.x,acc[2][3]); acc[2][3]=f2fma(h3.y,v2.y,acc[2][3]);
            acc[3][0]=f2fma(h0.x,v3.x,acc[3][0]); acc[3][0]=f2fma(h0.y,v3.y,acc[3][0]);
            acc[3][1]=f2fma(h1.x,v3.x,acc[3][1]); acc[3][1]=f2fma(h1.y,v3.y,acc[3][1]);
            acc[3][2]=f2fma(h2.x,v3.x,acc[3][2]); acc[3][2]=f2fma(h2.y,v3.y,acc[3][2]);
            acc[3][3]=f2fma(h3.x,v3.x,acc[3][3]); acc[3][3]=f2fma(h3.y,v3.y,acc[3][3]);
        }

        // ---- partials: shR[(g*4+j)*527 + kh*33 + lane] ----
        #pragma unroll
        for (int g = 0; g < 4; g++)
            #pragma unroll
            for (int j = 0; j < 4; j++)
                shR[(g*4 + j) * 527 + kh * 33 + lane] = hadd(acc[g][j]);
        __syncthreads();                   // bar1: all partials in

        // ---- reduce (warp = gate x dim, lane = batch) + bias + nonlin ----
        {
            float s = shB[rg * 4 + rd];
            #pragma unroll
            for (int k = 0; k < 16; k++) s += rp[k * 33];
            shG[rg * 128 + rd * 32 + lane] = (rg == 2) ? tanhfast(s) : sigf(s);
        }
        __syncthreads();                   // bar2: gates ready

        // ---- owners (warps 0-3): c/h update, owners-only bar, release ----
        if (tid < 128){
            float iv = shG[  0 + pd * 32 + pb];
            float fv = shG[128 + pd * 32 + pb];
            float gv = shG[256 + pd * 32 + pb];
            float ov = shG[384 + pd * 32 + pb];
            cc = fv * cc + iv * gv;
            float hv = ov * tanhfast(cc);
            g_hbuf[t + 1][hwidx] = hv;
            asm volatile("bar.sync 3, 128;");          // owners only
            if (tid == 0 && t + 1 < TT)
                st_release(&g_flag[bx * 8], (unsigned)(t + 1));
        }
        // warps 4-15 skip straight to step t+1: their next shared write
        // (shR/shG at t+1) is ordered behind bar1(t+1), which requires
        // warps 0-3 and therefore the owner tail above. No block bar.
    }
}

// =====================================================================
extern "C" void kernel_launch(void* const* d_in, const int* in_sizes, int n_in,
                              void* d_out, int out_size)
{
    (void)in_sizes; (void)n_in; (void)out_size;
    const float* x    = (const float*)d_in[0];
    const float* Wih  = (const float*)d_in[1];
    const float* Whh  = (const float*)d_in[2];
    const float* bih  = (const float*)d_in[3];
    const float* bhh  = (const float*)d_in[4];
    float* out = (float*)d_out;

    // 16384 + 16384 + 16384 + 8432 + 512 + 16 = 58112 floats = 232448 bytes
    cudaFuncSetAttribute(lstm_rec_kernel,
                         cudaFuncAttributeMaxDynamicSharedMemorySize, 232448);

    xt_kernel<<<(TT * DIM * BATCH / 4) / 256, 256>>>(x);
    lstm_rec_kernel<<<NBLK, RTHR, 232448>>>(Wih, Whh, bih, bhh);
    out_kernel<<<(BATCH * TT * DIM / 4) / 256, 256>>>(out);
}